// round 13
// baseline (speedup 1.0000x reference)
#include <cuda_runtime.h>

// PINN via tabulated jets. Quad-cooperative interpolation from a shared-mem
// table with 80B node stride (kills the 64B-stride bank-parity conflicts
// that sank the earlier smem attempt). 257 nodes (h=2^-8), node = 4
// overlapping float4 groups + 16B pad:
//  g0=(u0,u1,u2,u3) g1=(u3,u4,w0,w1) g2=(w1,w2,w3,w4) g3=(w3,w4,w5,w6)
// Kernel A: order-6 jets, 8 threads/node. Kernel B: persistent, 4 lanes per
// point, 8 pts/quad batched, LDS.128 gather, 2 seam shuffles, float2 stores.
// Outputs: [u,u_x,u_xx,w,w_x,w_xx,w_xxx,w_xxxx].

#define KNODES 257
#define HINV   256.0f
#define HF     0.00390625f       // 2^-8 exact
#define MAGIC  12582912.0f       // 1.5 * 2^23
#define NSTRIDE 5                // float4s per node (80B)

__device__ __align__(128) float4 g_tab[KNODES * NSTRIDE];

__device__ __forceinline__ float tanh_fast(float z, float& s) {
    float e, r;
    asm("ex2.approx.f32 %0, %1;" : "=f"(e) : "f"(z * 2.8853900817779268f));
    asm("rcp.approx.f32 %0, %1;" : "=f"(r) : "f"(e + 1.0f));
    float t = fmaf(-2.0f, r, 1.0f);
    s = fmaf(-t, t, 1.0f);
    return t;
}

// ---------------- Kernel A: order-6 jets, 8 threads per node ----------------

__global__ __launch_bounds__(256)
void pinn_build_table(const float* __restrict__ gW0, const float* __restrict__ gb0,
                      const float* __restrict__ gW1, const float* __restrict__ gb1,
                      const float* __restrict__ gW2, const float* __restrict__ gb2)
{
    const unsigned FULL = 0xffffffffu;
    int gtid = blockIdx.x * blockDim.x + threadIdx.x;
    int node = gtid >> 3;
    int s    = gtid & 7;
    bool live = node < KNODES;
    int nodec = live ? node : KNODES - 1;

    const float x0 = (float)nodec * HF;

    // Layer 0 jet for neuron s
    float h0, h1, h2, h3, h4, h5, h6;
    {
        float w = gW0[s];
        float z = fmaf(w, x0, gb0[s]);
        float sg;
        float t = tanh_fast(z, sg);
        float t2 = t * t;
        float d2 = -2.0f * t * sg;
        float d3 = sg * (6.0f * t2 - 2.0f);
        float d4 = t * sg * (16.0f - 24.0f * t2);
        float d5 = sg * (16.0f + t2 * (-120.0f + 120.0f * t2));
        float d6 = sg * t * (-272.0f + t2 * (960.0f - 720.0f * t2));
        float w2 = w * w, w3 = w2 * w;
        h0 = t;      h1 = sg * w;  h2 = d2 * w2; h3 = d3 * w3;
        h4 = d4 * w2 * w2; h5 = d5 * w2 * w3; h6 = d6 * w3 * w3;
    }

    // Layer 1 row s via width-8 shuffles
    float z0 = gb1[s], z1 = 0.f, z2 = 0.f, z3 = 0.f, z4 = 0.f, z5 = 0.f, z6 = 0.f;
#pragma unroll
    for (int k = 0; k < 8; ++k) {
        float wk = gW1[s * 8 + k];
        z0 = fmaf(wk, __shfl_sync(FULL, h0, k, 8), z0);
        z1 = fmaf(wk, __shfl_sync(FULL, h1, k, 8), z1);
        z2 = fmaf(wk, __shfl_sync(FULL, h2, k, 8), z2);
        z3 = fmaf(wk, __shfl_sync(FULL, h3, k, 8), z3);
        z4 = fmaf(wk, __shfl_sync(FULL, h4, k, 8), z4);
        z5 = fmaf(wk, __shfl_sync(FULL, h5, k, 8), z5);
        z6 = fmaf(wk, __shfl_sync(FULL, h6, k, 8), z6);
    }

    // tanh jet + Faa di Bruno to order 6
    float g0, g1, g2, g3, g4, g5, g6;
    {
        float sg;
        float t = tanh_fast(z0, sg);
        float t2 = t * t;
        float d1 = sg;
        float d2 = -2.0f * t * sg;
        float d3 = sg * (6.0f * t2 - 2.0f);
        float d4 = t * sg * (16.0f - 24.0f * t2);
        float d5 = sg * (16.0f + t2 * (-120.0f + 120.0f * t2));
        float d6 = sg * t * (-272.0f + t2 * (960.0f - 720.0f * t2));

        float z1_2 = z1 * z1, z1_3 = z1_2 * z1, z1_4 = z1_2 * z1_2;
        g0 = t;
        g1 = d1 * z1;
        g2 = d1 * z2 + d2 * z1_2;
        g3 = d1 * z3 + 3.0f * d2 * z1 * z2 + d3 * z1_3;
        g4 = d1 * z4 + d2 * (4.0f * z1 * z3 + 3.0f * z2 * z2)
           + 6.0f * d3 * z1_2 * z2 + d4 * z1_4;
        g5 = d1 * z5 + d2 * (5.0f * z1 * z4 + 10.0f * z2 * z3)
           + d3 * (10.0f * z1_2 * z3 + 15.0f * z1 * z2 * z2)
           + 10.0f * d4 * z1_3 * z2 + d5 * z1_4 * z1;
        g6 = d1 * z6 + d2 * (6.0f * z1 * z5 + 15.0f * z2 * z4 + 10.0f * z3 * z3)
           + d3 * (15.0f * z1_2 * z4 + 60.0f * z1 * z2 * z3 + 15.0f * z2 * z2 * z2)
           + d4 * (20.0f * z1_3 * z3 + 45.0f * z1_2 * z2 * z2)
           + 15.0f * d5 * z1_4 * z2 + d6 * z1_4 * z1_2;
    }

    // output taps + butterfly reduce over octet
    float wu = gW2[s], ww = gW2[8 + s];
    float U0 = wu * g0, U1 = wu * g1, U2 = wu * g2, U3 = wu * g3, U4 = wu * g4;
    float V0 = ww * g0, V1 = ww * g1, V2 = ww * g2, V3 = ww * g3,
          V4 = ww * g4, V5 = ww * g5, V6 = ww * g6;
#pragma unroll
    for (int off = 4; off >= 1; off >>= 1) {
        U0 += __shfl_xor_sync(FULL, U0, off, 8);
        U1 += __shfl_xor_sync(FULL, U1, off, 8);
        U2 += __shfl_xor_sync(FULL, U2, off, 8);
        U3 += __shfl_xor_sync(FULL, U3, off, 8);
        U4 += __shfl_xor_sync(FULL, U4, off, 8);
        V0 += __shfl_xor_sync(FULL, V0, off, 8);
        V1 += __shfl_xor_sync(FULL, V1, off, 8);
        V2 += __shfl_xor_sync(FULL, V2, off, 8);
        V3 += __shfl_xor_sync(FULL, V3, off, 8);
        V4 += __shfl_xor_sync(FULL, V4, off, 8);
        V5 += __shfl_xor_sync(FULL, V5, off, 8);
        V6 += __shfl_xor_sync(FULL, V6, off, 8);
    }
    U0 += gb2[0];
    V0 += gb2[1];

    if (live && s < 4) {
        float4 v;
        switch (s) {
            case 0:  v = make_float4(U0, U1, U2, U3); break;
            case 1:  v = make_float4(U3, U4, V0, V1); break;
            case 2:  v = make_float4(V1, V2, V3, V4); break;
            default: v = make_float4(V3, V4, V5, V6); break;
        }
        g_tab[node * NSTRIDE + s] = v;
    }
}

// ---------------- Kernel B: persistent, smem table (80B stride) ------------

#define IB     512
#define IGRID  592                          // 4 blocks/SM * 148
#define PPQ    8                            // points per quad; warp = 64 pts
#define TW     ((IGRID * IB) / 32)          // total warps
#define SMEM_F4 (KNODES * NSTRIDE)          // 1285 float4 = 20560 B

__global__ __launch_bounds__(IB, 4)
void pinn_interp(const float* __restrict__ x, float* __restrict__ out, int n)
{
    extern __shared__ __align__(16) float4 s_tbl[];

    // stage table once per block (20.6KB)
    for (int idx = threadIdx.x; idx < SMEM_F4; idx += IB)
        s_tbl[idx] = g_tab[idx];
    __syncthreads();

    const int lane = threadIdx.x & 31;
    const int sub  = lane & 3;
    const int lb   = lane & ~3;
    const int quad = lane >> 2;              // 0..7
    const int wid  = (blockIdx.x * IB + threadIdx.x) >> 5;

    for (int chunk = wid; chunk * 64 < n; chunk += TW) {
        const int wbase = chunk * 64;

        // ---- Phase 1: batched x loads ----
        float xv[PPQ];
#pragma unroll
        for (int k = 0; k < PPQ; ++k) {
            int p  = wbase + 8 * k + quad;
            int pc = p < n ? p : n - 1;
            xv[k] = __ldg(x + pc);
        }

        // ---- Phase 2: index math + batched smem gathers ----
        float dx[PPQ];
        int   idx[PPQ];
#pragma unroll
        for (int k = 0; k < PPQ; ++k) {
            float tm = fmaf(xv[k], HINV, MAGIC);
            int jn = __float_as_int(tm) & 0x1FF;
            float fj = tm - MAGIC;
            dx[k] = fmaf(fj, -HF, xv[k]);
            idx[k] = jn * NSTRIDE + sub;
        }
        float4 f[PPQ];
#pragma unroll
        for (int k = 0; k < PPQ; ++k)
            f[k] = s_tbl[idx[k]];

        // ---- Phase 3: seam shuffles, Taylor, coalesced stores ----
#pragma unroll
        for (int k = 0; k < PPQ; ++k) {
            float t2 = 0.5f * dx[k] * dx[k];
            float sz = __shfl_sync(0xffffffffu, f[k].z, lb);      // u2 from sub0
            float sy = __shfl_sync(0xffffffffu, f[k].y, lb + 2);  // w2 from sub2

            float oA, oB;
            if (sub == 1) {
                oA = fmaf(t2, f[k].y, fmaf(dx[k], f[k].x, sz));     // u_xx
                oB = fmaf(t2, sy,     fmaf(dx[k], f[k].w, f[k].z)); // w
            } else {
                oA = fmaf(t2, f[k].z, fmaf(dx[k], f[k].y, f[k].x));
                oB = fmaf(t2, f[k].w, fmaf(dx[k], f[k].z, f[k].y));
            }

            int p = wbase + 8 * k + quad;
            if (p < n) {
                float2* op = reinterpret_cast<float2*>(out + (size_t)p * 8) + sub;
                *op = make_float2(oA, oB);
            }
        }
    }
}

extern "C" void kernel_launch(void* const* d_in, const int* in_sizes, int n_in,
                              void* d_out, int out_size)
{
    const float* x  = (const float*)d_in[0];
    const float* W0 = (const float*)d_in[1];
    const float* b0 = (const float*)d_in[2];
    const float* W1 = (const float*)d_in[3];
    const float* b1 = (const float*)d_in[4];
    const float* W2 = (const float*)d_in[5];
    const float* b2 = (const float*)d_in[6];
    float* out = (float*)d_out;

    int n = in_sizes[0];

    int build_threads = KNODES * 8;   // 2056
    pinn_build_table<<<(build_threads + 255) / 256, 256>>>(W0, b0, W1, b1, W2, b2);

    pinn_interp<<<IGRID, IB, SMEM_F4 * (int)sizeof(float4)>>>(x, out, n);
}

// round 14
// speedup vs baseline: 2.8117x; 2.8117x over previous
#include <cuda_runtime.h>

// PINN via tabulated jets, quad-cooperative interpolation (LDG gather —
// measured to be at the L1tex wavefront floor; smem variants all lose).
// Table: 257 nodes (h=2^-8), 64B/node, 4 overlapping float4 groups:
//  g0=(u0,u1,u2,u3) g1=(u3,u4,w0,w1) g2=(w1,w2,w3,w4) g3=(w3,w4,w5,w6)
// Kernel A: order-6 jets, 8 threads/node. Kernel B: 4 lanes/point, 8 pts
// per quad batched, one LDG.128 per lane per point, 2 seam shuffles,
// coalesced float2 stores; clamp-free fast path for full warps.
// Outputs: [u,u_x,u_xx,w,w_x,w_xx,w_xxx,w_xxxx].

#define KNODES 257
#define HINV   256.0f
#define HF     0.00390625f       // 2^-8 exact
#define MAGIC  12582912.0f       // 1.5 * 2^23

__device__ __align__(128) float4 g_tab4[KNODES * 4];

__device__ __forceinline__ float tanh_fast(float z, float& s) {
    float e, r;
    asm("ex2.approx.f32 %0, %1;" : "=f"(e) : "f"(z * 2.8853900817779268f));
    asm("rcp.approx.f32 %0, %1;" : "=f"(r) : "f"(e + 1.0f));
    float t = fmaf(-2.0f, r, 1.0f);
    s = fmaf(-t, t, 1.0f);
    return t;
}

// ---------------- Kernel A: order-6 jets, 8 threads per node ----------------

__global__ __launch_bounds__(256)
void pinn_build_table(const float* __restrict__ gW0, const float* __restrict__ gb0,
                      const float* __restrict__ gW1, const float* __restrict__ gb1,
                      const float* __restrict__ gW2, const float* __restrict__ gb2)
{
    const unsigned FULL = 0xffffffffu;
    int gtid = blockIdx.x * blockDim.x + threadIdx.x;
    int node = gtid >> 3;
    int s    = gtid & 7;
    bool live = node < KNODES;
    int nodec = live ? node : KNODES - 1;

    const float x0 = (float)nodec * HF;

    // Layer 0 jet for neuron s
    float h0, h1, h2, h3, h4, h5, h6;
    {
        float w = gW0[s];
        float z = fmaf(w, x0, gb0[s]);
        float sg;
        float t = tanh_fast(z, sg);
        float t2 = t * t;
        float d2 = -2.0f * t * sg;
        float d3 = sg * (6.0f * t2 - 2.0f);
        float d4 = t * sg * (16.0f - 24.0f * t2);
        float d5 = sg * (16.0f + t2 * (-120.0f + 120.0f * t2));
        float d6 = sg * t * (-272.0f + t2 * (960.0f - 720.0f * t2));
        float w2 = w * w, w3 = w2 * w;
        h0 = t;      h1 = sg * w;  h2 = d2 * w2; h3 = d3 * w3;
        h4 = d4 * w2 * w2; h5 = d5 * w2 * w3; h6 = d6 * w3 * w3;
    }

    // Layer 1 row s via width-8 shuffles
    float z0 = gb1[s], z1 = 0.f, z2 = 0.f, z3 = 0.f, z4 = 0.f, z5 = 0.f, z6 = 0.f;
#pragma unroll
    for (int k = 0; k < 8; ++k) {
        float wk = gW1[s * 8 + k];
        z0 = fmaf(wk, __shfl_sync(FULL, h0, k, 8), z0);
        z1 = fmaf(wk, __shfl_sync(FULL, h1, k, 8), z1);
        z2 = fmaf(wk, __shfl_sync(FULL, h2, k, 8), z2);
        z3 = fmaf(wk, __shfl_sync(FULL, h3, k, 8), z3);
        z4 = fmaf(wk, __shfl_sync(FULL, h4, k, 8), z4);
        z5 = fmaf(wk, __shfl_sync(FULL, h5, k, 8), z5);
        z6 = fmaf(wk, __shfl_sync(FULL, h6, k, 8), z6);
    }

    // tanh jet + Faa di Bruno to order 6
    float g0, g1, g2, g3, g4, g5, g6;
    {
        float sg;
        float t = tanh_fast(z0, sg);
        float t2 = t * t;
        float d1 = sg;
        float d2 = -2.0f * t * sg;
        float d3 = sg * (6.0f * t2 - 2.0f);
        float d4 = t * sg * (16.0f - 24.0f * t2);
        float d5 = sg * (16.0f + t2 * (-120.0f + 120.0f * t2));
        float d6 = sg * t * (-272.0f + t2 * (960.0f - 720.0f * t2));

        float z1_2 = z1 * z1, z1_3 = z1_2 * z1, z1_4 = z1_2 * z1_2;
        g0 = t;
        g1 = d1 * z1;
        g2 = d1 * z2 + d2 * z1_2;
        g3 = d1 * z3 + 3.0f * d2 * z1 * z2 + d3 * z1_3;
        g4 = d1 * z4 + d2 * (4.0f * z1 * z3 + 3.0f * z2 * z2)
           + 6.0f * d3 * z1_2 * z2 + d4 * z1_4;
        g5 = d1 * z5 + d2 * (5.0f * z1 * z4 + 10.0f * z2 * z3)
           + d3 * (10.0f * z1_2 * z3 + 15.0f * z1 * z2 * z2)
           + 10.0f * d4 * z1_3 * z2 + d5 * z1_4 * z1;
        g6 = d1 * z6 + d2 * (6.0f * z1 * z5 + 15.0f * z2 * z4 + 10.0f * z3 * z3)
           + d3 * (15.0f * z1_2 * z4 + 60.0f * z1 * z2 * z3 + 15.0f * z2 * z2 * z2)
           + d4 * (20.0f * z1_3 * z3 + 45.0f * z1_2 * z2 * z2)
           + 15.0f * d5 * z1_4 * z2 + d6 * z1_4 * z1_2;
    }

    // output taps + butterfly reduce over octet
    float wu = gW2[s], ww = gW2[8 + s];
    float U0 = wu * g0, U1 = wu * g1, U2 = wu * g2, U3 = wu * g3, U4 = wu * g4;
    float V0 = ww * g0, V1 = ww * g1, V2 = ww * g2, V3 = ww * g3,
          V4 = ww * g4, V5 = ww * g5, V6 = ww * g6;
#pragma unroll
    for (int off = 4; off >= 1; off >>= 1) {
        U0 += __shfl_xor_sync(FULL, U0, off, 8);
        U1 += __shfl_xor_sync(FULL, U1, off, 8);
        U2 += __shfl_xor_sync(FULL, U2, off, 8);
        U3 += __shfl_xor_sync(FULL, U3, off, 8);
        U4 += __shfl_xor_sync(FULL, U4, off, 8);
        V0 += __shfl_xor_sync(FULL, V0, off, 8);
        V1 += __shfl_xor_sync(FULL, V1, off, 8);
        V2 += __shfl_xor_sync(FULL, V2, off, 8);
        V3 += __shfl_xor_sync(FULL, V3, off, 8);
        V4 += __shfl_xor_sync(FULL, V4, off, 8);
        V5 += __shfl_xor_sync(FULL, V5, off, 8);
        V6 += __shfl_xor_sync(FULL, V6, off, 8);
    }
    U0 += gb2[0];
    V0 += gb2[1];

    if (live && s < 4) {
        float4 v;
        switch (s) {
            case 0:  v = make_float4(U0, U1, U2, U3); break;
            case 1:  v = make_float4(U3, U4, V0, V1); break;
            case 2:  v = make_float4(V1, V2, V3, V4); break;
            default: v = make_float4(V3, V4, V5, V6); break;
        }
        g_tab4[node * 4 + s] = v;
    }
}

// ---------------- Kernel B: quad-cooperative, 8 pts/quad, fast path --------

#define IB   256
#define PPQ  8     // points per quad; warp covers 64 points

__global__ __launch_bounds__(IB)
void pinn_interp(const float* __restrict__ x, float* __restrict__ out, int n)
{
    const int lane  = threadIdx.x & 31;
    const int sub   = lane & 3;
    const int lb    = lane & ~3;
    const int quad  = lane >> 2;               // 0..7
    const int wid   = (blockIdx.x * IB + threadIdx.x) >> 5;
    const int wbase = wid * (8 * PPQ);         // 64 points per warp

    const bool full = (wbase + 8 * PPQ) <= n;

    // ---- Phase 1: batched x loads ----
    float xv[PPQ];
    if (full) {
#pragma unroll
        for (int k = 0; k < PPQ; ++k)
            xv[k] = __ldg(x + wbase + 8 * k + quad);
    } else {
#pragma unroll
        for (int k = 0; k < PPQ; ++k) {
            int p  = wbase + 8 * k + quad;
            int pc = p < n ? p : n - 1;
            xv[k] = __ldg(x + pc);
        }
    }

    // ---- Phase 2: index math (+ t2 off the load-dependent chain) ----
    float dx[PPQ], t2[PPQ];
    int   jn[PPQ];
#pragma unroll
    for (int k = 0; k < PPQ; ++k) {
        float tm = fmaf(xv[k], HINV, MAGIC);
        jn[k] = __float_as_int(tm) & 0x1FF;
        float fj = tm - MAGIC;
        dx[k] = fmaf(fj, -HF, xv[k]);
        t2[k] = 0.5f * dx[k] * dx[k];
    }
    float4 f[PPQ];
#pragma unroll
    for (int k = 0; k < PPQ; ++k)
        f[k] = __ldg(&g_tab4[jn[k] * 4 + sub]);

    // ---- Phase 3: seam shuffles, Taylor, coalesced stores ----
#pragma unroll
    for (int k = 0; k < PPQ; ++k) {
        float sz = __shfl_sync(0xffffffffu, f[k].z, lb);      // u2 from sub0
        float sy = __shfl_sync(0xffffffffu, f[k].y, lb + 2);  // w2 from sub2

        float oA, oB;
        if (sub == 1) {
            oA = fmaf(t2[k], f[k].y, fmaf(dx[k], f[k].x, sz));     // u_xx
            oB = fmaf(t2[k], sy,     fmaf(dx[k], f[k].w, f[k].z)); // w
        } else {
            oA = fmaf(t2[k], f[k].z, fmaf(dx[k], f[k].y, f[k].x));
            oB = fmaf(t2[k], f[k].w, fmaf(dx[k], f[k].z, f[k].y));
        }

        int p = wbase + 8 * k + quad;
        if (full || p < n) {
            float2* op = reinterpret_cast<float2*>(out + (size_t)p * 8) + sub;
            *op = make_float2(oA, oB);
        }
    }
}

extern "C" void kernel_launch(void* const* d_in, const int* in_sizes, int n_in,
                              void* d_out, int out_size)
{
    const float* x  = (const float*)d_in[0];
    const float* W0 = (const float*)d_in[1];
    const float* b0 = (const float*)d_in[2];
    const float* W1 = (const float*)d_in[3];
    const float* b1 = (const float*)d_in[4];
    const float* W2 = (const float*)d_in[5];
    const float* b2 = (const float*)d_in[6];
    float* out = (float*)d_out;

    int n = in_sizes[0];

    int build_threads = KNODES * 8;   // 2056
    pinn_build_table<<<(build_threads + 255) / 256, 256>>>(W0, b0, W1, b1, W2, b2);

    int pts_per_block = (IB / 32) * 8 * PPQ;   // 512 points per block
    int blocks = (n + pts_per_block - 1) / pts_per_block;
    pinn_interp<<<blocks, IB>>>(x, out, n);
}

// round 15
// speedup vs baseline: 2.8497x; 1.0135x over previous
#include <cuda_runtime.h>

// PINN via tabulated jets, quad-cooperative interpolation (LDG gather — at
// the measured L1tex wavefront floor). Table: 257 nodes (h=2^-8), 64B/node,
// 4 overlapping float4 groups:
//  g0=(u0,u1,u2,u3) g1=(u3,u4,w0,w1) g2=(w1,w2,w3,w4) g3=(w3,w4,w5,w6)
// Kernel A: order-6 jets, 8 threads/node, 64-thread blocks (spread), signals
// dependents via PDL. Kernel B: launched with PDL; x-loads + index math run
// before griddepcontrol.wait, table gather after. 4 lanes/point, 8 pts/quad.
// Outputs: [u,u_x,u_xx,w,w_x,w_xx,w_xxx,w_xxxx].

#define KNODES 257
#define HINV   256.0f
#define HF     0.00390625f       // 2^-8 exact
#define MAGIC  12582912.0f       // 1.5 * 2^23

__device__ __align__(128) float4 g_tab4[KNODES * 4];

__device__ __forceinline__ float tanh_fast(float z, float& s) {
    float e, r;
    asm("ex2.approx.f32 %0, %1;" : "=f"(e) : "f"(z * 2.8853900817779268f));
    asm("rcp.approx.f32 %0, %1;" : "=f"(r) : "f"(e + 1.0f));
    float t = fmaf(-2.0f, r, 1.0f);
    s = fmaf(-t, t, 1.0f);
    return t;
}

// ---------------- Kernel A: order-6 jets, 8 threads per node ----------------

__global__ __launch_bounds__(64)
void pinn_build_table(const float* __restrict__ gW0, const float* __restrict__ gb0,
                      const float* __restrict__ gW1, const float* __restrict__ gb1,
                      const float* __restrict__ gW2, const float* __restrict__ gb2)
{
    const unsigned FULL = 0xffffffffu;
    int gtid = blockIdx.x * blockDim.x + threadIdx.x;
    int node = gtid >> 3;
    int s    = gtid & 7;
    bool live = node < KNODES;
    int nodec = live ? node : KNODES - 1;

    const float x0 = (float)nodec * HF;

    // Layer 0 jet for neuron s
    float h0, h1, h2, h3, h4, h5, h6;
    {
        float w = gW0[s];
        float z = fmaf(w, x0, gb0[s]);
        float sg;
        float t = tanh_fast(z, sg);
        float t2 = t * t;
        float d2 = -2.0f * t * sg;
        float d3 = sg * (6.0f * t2 - 2.0f);
        float d4 = t * sg * (16.0f - 24.0f * t2);
        float d5 = sg * (16.0f + t2 * (-120.0f + 120.0f * t2));
        float d6 = sg * t * (-272.0f + t2 * (960.0f - 720.0f * t2));
        float w2 = w * w, w3 = w2 * w;
        h0 = t;      h1 = sg * w;  h2 = d2 * w2; h3 = d3 * w3;
        h4 = d4 * w2 * w2; h5 = d5 * w2 * w3; h6 = d6 * w3 * w3;
    }

    // Layer 1 row s via width-8 shuffles
    float z0 = gb1[s], z1 = 0.f, z2 = 0.f, z3 = 0.f, z4 = 0.f, z5 = 0.f, z6 = 0.f;
#pragma unroll
    for (int k = 0; k < 8; ++k) {
        float wk = gW1[s * 8 + k];
        z0 = fmaf(wk, __shfl_sync(FULL, h0, k, 8), z0);
        z1 = fmaf(wk, __shfl_sync(FULL, h1, k, 8), z1);
        z2 = fmaf(wk, __shfl_sync(FULL, h2, k, 8), z2);
        z3 = fmaf(wk, __shfl_sync(FULL, h3, k, 8), z3);
        z4 = fmaf(wk, __shfl_sync(FULL, h4, k, 8), z4);
        z5 = fmaf(wk, __shfl_sync(FULL, h5, k, 8), z5);
        z6 = fmaf(wk, __shfl_sync(FULL, h6, k, 8), z6);
    }

    // tanh jet + Faa di Bruno to order 6
    float g0, g1, g2, g3, g4, g5, g6;
    {
        float sg;
        float t = tanh_fast(z0, sg);
        float t2 = t * t;
        float d1 = sg;
        float d2 = -2.0f * t * sg;
        float d3 = sg * (6.0f * t2 - 2.0f);
        float d4 = t * sg * (16.0f - 24.0f * t2);
        float d5 = sg * (16.0f + t2 * (-120.0f + 120.0f * t2));
        float d6 = sg * t * (-272.0f + t2 * (960.0f - 720.0f * t2));

        float z1_2 = z1 * z1, z1_3 = z1_2 * z1, z1_4 = z1_2 * z1_2;
        g0 = t;
        g1 = d1 * z1;
        g2 = d1 * z2 + d2 * z1_2;
        g3 = d1 * z3 + 3.0f * d2 * z1 * z2 + d3 * z1_3;
        g4 = d1 * z4 + d2 * (4.0f * z1 * z3 + 3.0f * z2 * z2)
           + 6.0f * d3 * z1_2 * z2 + d4 * z1_4;
        g5 = d1 * z5 + d2 * (5.0f * z1 * z4 + 10.0f * z2 * z3)
           + d3 * (10.0f * z1_2 * z3 + 15.0f * z1 * z2 * z2)
           + 10.0f * d4 * z1_3 * z2 + d5 * z1_4 * z1;
        g6 = d1 * z6 + d2 * (6.0f * z1 * z5 + 15.0f * z2 * z4 + 10.0f * z3 * z3)
           + d3 * (15.0f * z1_2 * z4 + 60.0f * z1 * z2 * z3 + 15.0f * z2 * z2 * z2)
           + d4 * (20.0f * z1_3 * z3 + 45.0f * z1_2 * z2 * z2)
           + 15.0f * d5 * z1_4 * z2 + d6 * z1_4 * z1_2;
    }

    // output taps + butterfly reduce over octet
    float wu = gW2[s], ww = gW2[8 + s];
    float U0 = wu * g0, U1 = wu * g1, U2 = wu * g2, U3 = wu * g3, U4 = wu * g4;
    float V0 = ww * g0, V1 = ww * g1, V2 = ww * g2, V3 = ww * g3,
          V4 = ww * g4, V5 = ww * g5, V6 = ww * g6;
#pragma unroll
    for (int off = 4; off >= 1; off >>= 1) {
        U0 += __shfl_xor_sync(FULL, U0, off, 8);
        U1 += __shfl_xor_sync(FULL, U1, off, 8);
        U2 += __shfl_xor_sync(FULL, U2, off, 8);
        U3 += __shfl_xor_sync(FULL, U3, off, 8);
        U4 += __shfl_xor_sync(FULL, U4, off, 8);
        V0 += __shfl_xor_sync(FULL, V0, off, 8);
        V1 += __shfl_xor_sync(FULL, V1, off, 8);
        V2 += __shfl_xor_sync(FULL, V2, off, 8);
        V3 += __shfl_xor_sync(FULL, V3, off, 8);
        V4 += __shfl_xor_sync(FULL, V4, off, 8);
        V5 += __shfl_xor_sync(FULL, V5, off, 8);
        V6 += __shfl_xor_sync(FULL, V6, off, 8);
    }
    U0 += gb2[0];
    V0 += gb2[1];

    if (live && s < 4) {
        float4 v;
        switch (s) {
            case 0:  v = make_float4(U0, U1, U2, U3); break;
            case 1:  v = make_float4(U3, U4, V0, V1); break;
            case 2:  v = make_float4(V1, V2, V3, V4); break;
            default: v = make_float4(V3, V4, V5, V6); break;
        }
        g_tab4[node * 4 + s] = v;
    }

    // PDL: table data is written; allow dependents to proceed.
    asm volatile("griddepcontrol.launch_dependents;");
}

// ---------------- Kernel B: quad-cooperative, 8 pts/quad, PDL ---------------

#define IB   256
#define PPQ  8     // points per quad; warp covers 64 points

__global__ __launch_bounds__(IB)
void pinn_interp(const float* __restrict__ x, float* __restrict__ out, int n)
{
    const int lane  = threadIdx.x & 31;
    const int sub   = lane & 3;
    const int lb    = lane & ~3;
    const int quad  = lane >> 2;               // 0..7
    const int wid   = (blockIdx.x * IB + threadIdx.x) >> 5;
    const int wbase = wid * (8 * PPQ);         // 64 points per warp

    const bool full = (wbase + 8 * PPQ) <= n;

    // ---- Phase 1: batched x loads (independent of the table) ----
    float xv[PPQ];
    if (full) {
#pragma unroll
        for (int k = 0; k < PPQ; ++k)
            xv[k] = __ldg(x + wbase + 8 * k + quad);
    } else {
#pragma unroll
        for (int k = 0; k < PPQ; ++k) {
            int p  = wbase + 8 * k + quad;
            int pc = p < n ? p : n - 1;
            xv[k] = __ldg(x + pc);
        }
    }

    // ---- Phase 2: index math (still table-independent) ----
    float dx[PPQ], t2[PPQ];
    int   jn[PPQ];
#pragma unroll
    for (int k = 0; k < PPQ; ++k) {
        float tm = fmaf(xv[k], HINV, MAGIC);
        jn[k] = __float_as_int(tm) & 0x1FF;
        float fj = tm - MAGIC;
        dx[k] = fmaf(fj, -HF, xv[k]);
        t2[k] = 0.5f * dx[k] * dx[k];
    }

    // PDL: wait for the build kernel's table before gathering from it.
    asm volatile("griddepcontrol.wait;");

    float4 f[PPQ];
#pragma unroll
    for (int k = 0; k < PPQ; ++k)
        f[k] = __ldg(&g_tab4[jn[k] * 4 + sub]);

    // ---- Phase 3: seam shuffles, Taylor, coalesced stores ----
#pragma unroll
    for (int k = 0; k < PPQ; ++k) {
        float sz = __shfl_sync(0xffffffffu, f[k].z, lb);      // u2 from sub0
        float sy = __shfl_sync(0xffffffffu, f[k].y, lb + 2);  // w2 from sub2

        float oA, oB;
        if (sub == 1) {
            oA = fmaf(t2[k], f[k].y, fmaf(dx[k], f[k].x, sz));     // u_xx
            oB = fmaf(t2[k], sy,     fmaf(dx[k], f[k].w, f[k].z)); // w
        } else {
            oA = fmaf(t2[k], f[k].z, fmaf(dx[k], f[k].y, f[k].x));
            oB = fmaf(t2[k], f[k].w, fmaf(dx[k], f[k].z, f[k].y));
        }

        int p = wbase + 8 * k + quad;
        if (full || p < n) {
            float2* op = reinterpret_cast<float2*>(out + (size_t)p * 8) + sub;
            *op = make_float2(oA, oB);
        }
    }
}

extern "C" void kernel_launch(void* const* d_in, const int* in_sizes, int n_in,
                              void* d_out, int out_size)
{
    const float* x  = (const float*)d_in[0];
    const float* W0 = (const float*)d_in[1];
    const float* b0 = (const float*)d_in[2];
    const float* W1 = (const float*)d_in[3];
    const float* b1 = (const float*)d_in[4];
    const float* W2 = (const float*)d_in[5];
    const float* b2 = (const float*)d_in[6];
    float* out = (float*)d_out;

    int n = in_sizes[0];

    // Build: 64-thread blocks spread over 33 SMs.
    int build_threads = KNODES * 8;   // 2056
    pinn_build_table<<<(build_threads + 63) / 64, 64>>>(W0, b0, W1, b1, W2, b2);

    // Interp: launched with PDL so its prologue overlaps the build tail.
    int pts_per_block = (IB / 32) * 8 * PPQ;   // 512 points per block
    int blocks = (n + pts_per_block - 1) / pts_per_block;

    cudaLaunchConfig_t cfg = {};
    cfg.gridDim  = dim3((unsigned)blocks, 1, 1);
    cfg.blockDim = dim3(IB, 1, 1);
    cfg.dynamicSmemBytes = 0;
    cfg.stream = 0;   // legacy default stream (same one the harness captures)
    cudaLaunchAttribute attrs[1];
    attrs[0].id = cudaLaunchAttributeProgrammaticStreamSerialization;
    attrs[0].val.programmaticStreamSerializationAllowed = 1;
    cfg.attrs = attrs;
    cfg.numAttrs = 1;

    cudaLaunchKernelEx(&cfg, pinn_interp, x, out, n);
}